// round 12
// baseline (speedup 1.0000x reference)
#include <cuda_runtime.h>
#include <cuda_bf16.h>
#include <cstdint>

// Problem constants: D=64, K=1024, N=65536.
#define DIM     64
#define MROWS   512          // rows per CTA (64 per warp, 4 m16 tiles)
#define NTILE   128          // codes per smem tile
#define MARGIN  4e-3f        // >> 2*||x||*||w||*2^-8*1.02 (worst ~7e-4)
#define MAXK    4096
#define XSTR    144          // smem bf16 row stride in bytes (64*2 padded to 9*16)

__device__ float g_c2[MAXK];   // ||w_k||^2, exact sequential fp32 (mul, add)

// ---- smem byte layout ----
#define SM_XS  0                          // X bf16: 512*144 = 73728
#define SM_WS  (MROWS * XSTR)             // W bf16 tile: 128*144 = 18432
#define SM_L2  (SM_WS + NTILE * XSTR)     // l2 per row: 512*4
#define SM_C2  (SM_L2 + MROWS * 4)        // c2 tile: 128*4
#define SM_TOT (SM_C2 + NTILE * 4)        // 94720 B

__device__ __forceinline__ uint32_t s2u(const void* p) {
    uint32_t a;
    asm("{ .reg .u64 t; cvta.to.shared.u64 t, %1; cvt.u32.u64 %0, t; }"
        : "=r"(a) : "l"(p));
    return a;
}

__device__ __forceinline__ void ldmx4(uint32_t& r0, uint32_t& r1, uint32_t& r2,
                                      uint32_t& r3, uint32_t addr) {
    asm volatile("ldmatrix.sync.aligned.m8n8.x4.shared.b16 {%0,%1,%2,%3}, [%4];"
                 : "=r"(r0), "=r"(r1), "=r"(r2), "=r"(r3) : "r"(addr));
}
__device__ __forceinline__ void ldmx2(uint32_t& r0, uint32_t& r1, uint32_t addr) {
    asm volatile("ldmatrix.sync.aligned.m8n8.x2.shared.b16 {%0,%1}, [%2];"
                 : "=r"(r0), "=r"(r1) : "r"(addr));
}

__device__ __forceinline__ void mma16816(float* d, const uint32_t* a,
                                         uint32_t b0, uint32_t b1) {
    asm volatile(
        "mma.sync.aligned.m16n8k16.row.col.f32.bf16.bf16.f32 "
        "{%0,%1,%2,%3}, {%4,%5,%6,%7}, {%8,%9}, {%0,%1,%2,%3};"
        : "+f"(d[0]), "+f"(d[1]), "+f"(d[2]), "+f"(d[3])
        : "r"(a[0]), "r"(a[1]), "r"(a[2]), "r"(a[3]), "r"(b0), "r"(b1));
}

__device__ __forceinline__ unsigned long long pack_bf16x4(float4 v) {
    return (unsigned long long)__bfloat16_as_ushort(__float2bfloat16(v.x))
         | ((unsigned long long)__bfloat16_as_ushort(__float2bfloat16(v.y)) << 16)
         | ((unsigned long long)__bfloat16_as_ushort(__float2bfloat16(v.z)) << 32)
         | ((unsigned long long)__bfloat16_as_ushort(__float2bfloat16(v.w)) << 48);
}

// exact dot: sequential fp32 FMA chain over d ascending (= reference rounding)
__device__ __noinline__ float exact_dot(const float* __restrict__ xr,
                                        const float* __restrict__ wr) {
    float cl = 0.0f;
#pragma unroll 8
    for (int d = 0; d < DIM; ++d)
        cl = __fmaf_rn(__ldg(xr + d), __ldg(wr + d), cl);
    return cl;
}

// ---------------------------------------------------------------------------
// C2[k] = sum_d W[k][d]^2, sequential (mul then add) — exact.
// ---------------------------------------------------------------------------
__global__ void c2_kernel(const float* __restrict__ W, int K) {
    int k = blockIdx.x * blockDim.x + threadIdx.x;
    if (k >= K) return;
    const float* w = W + k * DIM;
    float s = 0.0f;
#pragma unroll
    for (int d = 0; d < DIM; ++d)
        s = __fadd_rn(s, __fmul_rn(w[d], w[d]));
    g_c2[k] = s;
}

// ---------------------------------------------------------------------------
// Tensor-filtered VQ via legacy warp MMA (sm_80 path, runs on HMMA):
// bf16 mma.sync computes approx dots; any candidate within MARGIN of the
// running exact best gets an exact fp32 rescore (bit-identical to reference).
// ---------------------------------------------------------------------------
__global__ void __launch_bounds__(256, 1)
vq_mma_kernel(const float* __restrict__ X, const float* __restrict__ W,
              float* __restrict__ outQ, float* __restrict__ outI, int ntiles)
{
    extern __shared__ char smem[];
    float* l2s = (float*)(smem + SM_L2);
    float* c2s = (float*)(smem + SM_C2);

    const int tid  = threadIdx.x;
    const int lane = tid & 31;
    const int w    = tid >> 5;          // warp 0..7, rows w*64..w*64+63
    const int rowbase = blockIdx.x * MROWS;

    // ---- X prologue: 2 rows/thread -> bf16 smem (SW-free, 144B stride) + exact L2
    {
#pragma unroll
        for (int rr = 0; rr < 2; ++rr) {
            int row = 2 * tid + rr;
            const float4* src = (const float4*)(X + (size_t)(rowbase + row) * DIM);
            unsigned long long* dst = (unsigned long long*)(smem + SM_XS + row * XSTR);
            float s = 0.0f;
#pragma unroll
            for (int q = 0; q < 16; ++q) {
                float4 v = src[q];
                s = __fadd_rn(s, __fmul_rn(v.x, v.x));
                s = __fadd_rn(s, __fmul_rn(v.y, v.y));
                s = __fadd_rn(s, __fmul_rn(v.z, v.z));
                s = __fadd_rn(s, __fmul_rn(v.w, v.w));
                dst[q] = pack_bf16x4(v);
            }
            l2s[row] = s;
        }
    }
    __syncthreads();

    // ---- A fragments: 4 m16 tiles x 4 k-chunks, loaded once (64 regs) ----
    uint32_t afr[4][4][4];
    {
        int m = lane >> 3;                       // matrix id 0..3
        int rowin = (lane & 7) + (m & 1) * 8;    // row within m16 tile
        int khalf = (m >> 1) * 8;                // k offset within chunk
#pragma unroll
        for (int mt = 0; mt < 4; ++mt)
#pragma unroll
            for (int kc = 0; kc < 4; ++kc) {
                uint32_t addr = s2u(smem + SM_XS +
                                    (w * 64 + mt * 16 + rowin) * XSTR +
                                    (kc * 16 + khalf) * 2);
                ldmx4(afr[mt][kc][0], afr[mt][kc][1],
                      afr[mt][kc][2], afr[mt][kc][3], addr);
            }
    }

    // per-thread rows: lr = 2*mt + s  ->  row = w*64 + mt*16 + (lane>>2) + 8*s
    float l2loc[8];
#pragma unroll
    for (int mt = 0; mt < 4; ++mt)
#pragma unroll
        for (int s = 0; s < 2; ++s)
            l2loc[2 * mt + s] = l2s[w * 64 + mt * 16 + (lane >> 2) + 8 * s];

    float bestd[8];
    int   besti[8];
#pragma unroll
    for (int i = 0; i < 8; ++i) { bestd[i] = 3.4e38f; besti[i] = 0; }

    const int q2 = (lane & 3) * 2;   // col pair base within n8 chunk

    for (int t = 0; t < ntiles; ++t) {
        const int cb = t * NTILE;
        __syncthreads();   // prior epilogue done with c2s / ws

        // ---- W tile -> bf16 smem + c2 tile ----
        {
            int code = tid >> 1, half = tid & 1;
            const float4* src = (const float4*)(W + (size_t)(cb + code) * DIM + half * 32);
            unsigned long long* dst =
                (unsigned long long*)(smem + SM_WS + code * XSTR + half * 64);
#pragma unroll
            for (int q = 0; q < 8; ++q) dst[q] = pack_bf16x4(src[q]);
            if (tid < NTILE) c2s[tid] = g_c2[cb + tid];
        }
        __syncthreads();

#pragma unroll 1
        for (int nc = 0; nc < 16; ++nc) {
            float acc[4][4];
#pragma unroll
            for (int mt = 0; mt < 4; ++mt)
#pragma unroll
                for (int i = 0; i < 4; ++i) acc[mt][i] = 0.0f;

#pragma unroll
            for (int kc = 0; kc < 4; ++kc) {
                int t16 = lane & 15;
                int code = nc * 8 + (t16 & 7);
                int koff = kc * 16 + (t16 >> 3) * 8;
                uint32_t baddr = s2u(smem + SM_WS + code * XSTR + koff * 2);
                uint32_t b0, b1;
                ldmx2(b0, b1, baddr);
#pragma unroll
                for (int mt = 0; mt < 4; ++mt)
                    mma16816(acc[mt], afr[mt][kc], b0, b1);
            }

            // ---- epilogue: filter + exact rescore ----
            int code0 = cb + nc * 8 + q2;
            float c2a = c2s[nc * 8 + q2];
            float c2b = c2s[nc * 8 + q2 + 1];
#pragma unroll
            for (int mt = 0; mt < 4; ++mt) {
#pragma unroll
                for (int s = 0; s < 2; ++s) {
                    int lr = 2 * mt + s;
                    float l2v = l2loc[lr];
                    int grow = rowbase + w * 64 + mt * 16 + (lane >> 2) + 8 * s;
                    float d0 = acc[mt][2 * s];       // (row, code0)
                    float d1 = acc[mt][2 * s + 1];   // (row, code0+1)
                    float ad0 = __fmaf_rn(d0, -2.0f, l2v + c2a);
                    if (ad0 < bestd[lr] + MARGIN) {
                        float cl = exact_dot(X + (size_t)grow * DIM,
                                             W + (size_t)code0 * DIM);
                        float de = __fadd_rn(__fsub_rn(l2v, __fmul_rn(2.0f, cl)), c2a);
                        if (de < bestd[lr]) { bestd[lr] = de; besti[lr] = code0; }
                    }
                    float ad1 = __fmaf_rn(d1, -2.0f, l2v + c2b);
                    if (ad1 < bestd[lr] + MARGIN) {
                        float cl = exact_dot(X + (size_t)grow * DIM,
                                             W + (size_t)(code0 + 1) * DIM);
                        float de = __fadd_rn(__fsub_rn(l2v, __fmul_rn(2.0f, cl)), c2b);
                        if (de < bestd[lr]) { bestd[lr] = de; besti[lr] = code0 + 1; }
                    }
                }
            }
        }
    }

    // ---- cross-lane reduction: 4 lanes per row (lane%4), tie-break on index
    __syncthreads();                    // done reading ws/c2s; reuse ws for bidx
    int* bidx = (int*)(smem + SM_WS);
#pragma unroll
    for (int lr = 0; lr < 8; ++lr) {
        float bd = bestd[lr];
        int   bi = besti[lr];
#pragma unroll
        for (int off = 1; off <= 2; off <<= 1) {
            float od = __shfl_xor_sync(0xffffffffu, bd, off);
            int   oi = __shfl_xor_sync(0xffffffffu, bi, off);
            if (od < bd || (od == bd && oi < bi)) { bd = od; bi = oi; }
        }
        if ((lane & 3) == 0) {
            int mt = lr >> 1, s = lr & 1;
            int row = w * 64 + mt * 16 + (lane >> 2) + 8 * s;
            bidx[row] = bi;
            if (outI) outI[rowbase + row] = (float)bi;
        }
    }
    __syncthreads();

    // ---- gather quantized = W[closest]: 2 rows per thread ----
    if (outQ) {
#pragma unroll
        for (int rr = 0; rr < 2; ++rr) {
            int row = 2 * tid + rr;
            int idx = bidx[row];
            const float4* src = (const float4*)(W + (size_t)idx * DIM);
            float4* dst = (float4*)(outQ + (size_t)(rowbase + row) * DIM);
#pragma unroll
            for (int q = 0; q < 16; ++q) dst[q] = __ldg(src + q);
        }
    }
}

// ---------------------------------------------------------------------------
extern "C" void kernel_launch(void* const* d_in, const int* in_sizes, int n_in,
                              void* d_out, int out_size) {
    const float* X = (const float*)d_in[0];
    const float* W = (const float*)d_in[1];
    int N = in_sizes[0] / DIM;
    int K = in_sizes[1] / DIM;

    long long nd = (long long)N * DIM;
    float* outQ = nullptr;
    float* outI = nullptr;
    if ((long long)out_size >= nd + N) { outQ = (float*)d_out; outI = (float*)d_out + nd; }
    else if ((long long)out_size == nd) { outQ = (float*)d_out; }
    else { outI = (float*)d_out; }

    cudaFuncSetAttribute(vq_mma_kernel, cudaFuncAttributeMaxDynamicSharedMemorySize,
                         SM_TOT);

    c2_kernel<<<(K + 255) / 256, 256>>>(W, K);
    vq_mma_kernel<<<N / MROWS, 256, SM_TOT>>>(X, W, outQ, outI, K / NTILE);
}

// round 13
// speedup vs baseline: 8.2690x; 8.2690x over previous
#include <cuda_runtime.h>
#include <cstdint>

// Problem constants: D=64, K=1024, N=65536.
#define DIM   64
#define RPT   256        // rows per CTA (1 per thread)
#define NT    128        // codes per smem tile
#define CAP   24         // candidate buffer entries per row per tile
#define MAXK  4096

__device__ float g_c2[MAXK];       // ||w_k||^2, exact sequential fp32 chain
__device__ float g_l1w[MAXK];      // ||w_k||_1 (inflated)
__device__ float g_wmx[MAXK];      // max|w_k|
__device__ float g_stat[2];        // [0]=swmax (global max|W|), [1]=max_k l1w
__device__ int   g_wq[MAXK * 16];  // packed int8 codebook (4 per int32)

__device__ __forceinline__ int dp4a(int a, int b, int c) {
    int d;
    asm("dp4a.s32.s32 %0, %1, %2, %3;" : "=r"(d) : "r"(a), "r"(b), "r"(c));
    return d;
}

// ---------------------------------------------------------------------------
// prepA: per-code stats. c2 uses the exact sequential (mul, add) chain.
// ---------------------------------------------------------------------------
__global__ void prepA(const float* __restrict__ W, int K) {
    int k = blockIdx.x * blockDim.x + threadIdx.x;
    if (k >= K) return;
    const float* w = W + k * DIM;
    float c2 = 0.f, l1 = 0.f, mx = 0.f;
#pragma unroll
    for (int d = 0; d < DIM; ++d) {
        float v = w[d];
        c2 = __fadd_rn(c2, __fmul_rn(v, v));
        float a = fabsf(v);
        l1 += a;
        mx = fmaxf(mx, a);
    }
    g_c2[k]  = c2;
    g_l1w[k] = l1 * 1.0001f + 1e-12f;
    g_wmx[k] = mx;
}

// ---------------------------------------------------------------------------
// prepB: reduce per-code stats to global scalars (one CTA).
// ---------------------------------------------------------------------------
__global__ void prepB(int K) {
    __shared__ float sm[256], sl[256];
    int t = threadIdx.x;
    float mx = 0.f, l1m = 0.f;
    for (int k = t; k < K; k += 256) {
        mx  = fmaxf(mx, g_wmx[k]);
        l1m = fmaxf(l1m, g_l1w[k]);
    }
    sm[t] = mx; sl[t] = l1m;
    __syncthreads();
    for (int s = 128; s > 0; s >>= 1) {
        if (t < s) { sm[t] = fmaxf(sm[t], sm[t + s]); sl[t] = fmaxf(sl[t], sl[t + s]); }
        __syncthreads();
    }
    if (t == 0) { g_stat[0] = fmaxf(sm[0], 1e-30f); g_stat[1] = sl[0]; }
}

// ---------------------------------------------------------------------------
// prepC: quantize W to int8 with the global scale (deterministic rn).
// ---------------------------------------------------------------------------
__global__ void prepC(const float* __restrict__ W, int K) {
    int k = blockIdx.x * blockDim.x + threadIdx.x;
    if (k >= K) return;
    float s127 = 127.f / g_stat[0];
    const float* w = W + k * DIM;
#pragma unroll
    for (int i = 0; i < 16; ++i) {
        int p = 0;
#pragma unroll
        for (int b = 0; b < 4; ++b) {
            int q = __float2int_rn(w[i * 4 + b] * s127);
            q = max(-127, min(127, q));
            p |= (q & 0xff) << (8 * b);
        }
        g_wq[k * 16 + i] = p;
    }
}

// ---------------------------------------------------------------------------
// Main kernel: int8/dp4a filter + exact fp32 rescore.
// One row per thread; codes scanned ascending; candidates buffered in order
// and rescored with the exact sequential FMA chain -> bit-identical argmin.
// ---------------------------------------------------------------------------
__global__ void __launch_bounds__(256, 2)
vq_main(const float* __restrict__ X, const float* __restrict__ W,
        float* __restrict__ outQ, float* __restrict__ outI, int K)
{
    extern __shared__ char smem[];
    float* wsf = (float*)smem;                               // [128][64] fp32  32768 B
    int*   wqs = (int*)(smem + 32768);                       // [128][16] int    8192 B
    float* c2s = (float*)(smem + 32768 + 8192);              // [128]             512 B
    unsigned short* buf =
        (unsigned short*)(smem + 32768 + 8192 + 512);        // [256][CAP]      12288 B

    const int tid = threadIdx.x;
    const int row = blockIdx.x * RPT + tid;

    // ---- load x row into registers ----
    float xr[DIM];
    {
        const float4* src = (const float4*)(X + (size_t)row * DIM);
#pragma unroll
        for (int q = 0; q < 16; ++q) {
            float4 v = src[q];
            xr[q * 4 + 0] = v.x; xr[q * 4 + 1] = v.y;
            xr[q * 4 + 2] = v.z; xr[q * 4 + 3] = v.w;
        }
    }

    // ---- exact L2 chain (reference rounding) ----
    float l2r = 0.f;
#pragma unroll
    for (int d = 0; d < DIM; ++d)
        l2r = __fadd_rn(l2r, __fmul_rn(xr[d], xr[d]));

    // ---- row stats for the rigorous filter window ----
    float sx = 0.f, l1x = 0.f;
#pragma unroll
    for (int d = 0; d < DIM; ++d) { float a = fabsf(xr[d]); sx = fmaxf(sx, a); l1x += a; }
    sx = fmaxf(sx, 1e-30f);
    const float sw = g_stat[0], l1wmax = g_stat[1];
    const float invsx = sx * (1.f / 127.f), invsw = sw * (1.f / 127.f);
    const float dxm = 0.6f * invsx + 4e-6f * sx;   // per-elem x quant error bound
    const float dwm = 0.6f * invsw + 4e-6f * sw;   // per-elem w quant error bound
    const float c2max = 64.f * sw * sw;            // bound on c2 spread
    const float window = 1.5f * (2.f * (dxm * l1wmax + dwm * (l1x * 1.0001f + 64.f * dxm))
                                 + c2max + 1e-6f);
    const float F2 = 2.f * invsx * invsw;          // score units per int-dot unit
    int Wint = (int)ceilf(window / F2) + 2;
    if (Wint > (1 << 28)) Wint = 1 << 28;

    // ---- quantize x to packed int8 ----
    const float s127x = 127.f / sx;
    int xp[16];
#pragma unroll
    for (int i = 0; i < 16; ++i) {
        int p = 0;
#pragma unroll
        for (int b = 0; b < 4; ++b) {
            int q = __float2int_rn(xr[i * 4 + b] * s127x);
            q = max(-127, min(127, q));
            p |= (q & 0xff) << (8 * b);
        }
        xp[i] = p;
    }

    float bd = 3.4e38f;
    int   bi = 0;
    int   runmax = -(1 << 29);
    const int ntiles = K / NT;

    for (int t = 0; t < ntiles; ++t) {
        const int cb = t * NT;
        __syncthreads();   // prior tile's rescores done before restage

        // ---- stage W fp32 tile, int8 tile, c2 tile ----
        {
            const float4* wsrc = (const float4*)(W + (size_t)cb * DIM);
            float4* wdst = (float4*)wsf;
#pragma unroll
            for (int i = 0; i < 8; ++i) wdst[tid + 256 * i] = wsrc[tid + 256 * i];
            const int4* qsrc = (const int4*)(g_wq + cb * 16);
            int4* qdst = (int4*)wqs;
#pragma unroll
            for (int i = 0; i < 2; ++i) qdst[tid + 256 * i] = qsrc[tid + 256 * i];
            if (tid < NT) c2s[tid] = g_c2[cb + tid];
        }
        __syncthreads();

        int cnt = 0;

#define RESCORE(JL) do {                                                     \
            const float* wr_ = wsf + (JL) * DIM;                             \
            float cl_ = 0.f;                                                 \
            _Pragma("unroll")                                                \
            for (int d_ = 0; d_ < DIM; ++d_)                                 \
                cl_ = __fmaf_rn(xr[d_], wr_[d_], cl_);                       \
            float de_ = __fadd_rn(__fsub_rn(l2r, __fmul_rn(2.f, cl_)),       \
                                  c2s[JL]);                                  \
            if (de_ < bd) { bd = de_; bi = cb + (JL); }                      \
        } while (0)

        // ---- hot loop: int8 dots, branch-light candidate collection ----
#pragma unroll 2
        for (int j = 0; j < NT; ++j) {
            const int4* wq4 = (const int4*)(wqs + j * 16);   // broadcast LDS
            int4 a0 = wq4[0], a1 = wq4[1], a2 = wq4[2], a3 = wq4[3];
            int da = 0, db = 0;
            da = dp4a(xp[0],  a0.x, da); da = dp4a(xp[1],  a0.y, da);
            da = dp4a(xp[2],  a0.z, da); da = dp4a(xp[3],  a0.w, da);
            da = dp4a(xp[4],  a1.x, da); da = dp4a(xp[5],  a1.y, da);
            da = dp4a(xp[6],  a1.z, da); da = dp4a(xp[7],  a1.w, da);
            db = dp4a(xp[8],  a2.x, db); db = dp4a(xp[9],  a2.y, db);
            db = dp4a(xp[10], a2.z, db); db = dp4a(xp[11], a2.w, db);
            db = dp4a(xp[12], a3.x, db); db = dp4a(xp[13], a3.y, db);
            db = dp4a(xp[14], a3.z, db); db = dp4a(xp[15], a3.w, db);
            int doti = da + db;
            bool cand = (doti >= runmax - Wint);   // test BEFORE updating runmax
            runmax = max(runmax, doti);
            if (cand) {
                if (cnt == CAP) {                  // rare: flush in order, keep ordering
                    for (int i = 0; i < cnt; ++i) { int jl = buf[tid * CAP + i]; RESCORE(jl); }
                    cnt = 0;
                }
                buf[tid * CAP + cnt] = (unsigned short)j;
                ++cnt;
            }
        }

        // ---- deferred exact rescores (ascending order => first-index ties) ----
        for (int i = 0; i < cnt; ++i) { int jl = buf[tid * CAP + i]; RESCORE(jl); }
#undef RESCORE
    }

    // ---- outputs ----
    if (outI) outI[row] = (float)bi;
    if (outQ) {
        const float4* src = (const float4*)(W + (size_t)bi * DIM);
        float4* dst = (float4*)(outQ + (size_t)row * DIM);
#pragma unroll
        for (int q = 0; q < 16; ++q) dst[q] = __ldg(src + q);
    }
}

// ---------------------------------------------------------------------------
extern "C" void kernel_launch(void* const* d_in, const int* in_sizes, int n_in,
                              void* d_out, int out_size) {
    const float* X = (const float*)d_in[0];
    const float* W = (const float*)d_in[1];
    int N = in_sizes[0] / DIM;
    int K = in_sizes[1] / DIM;

    long long nd = (long long)N * DIM;
    float* outQ = nullptr;
    float* outI = nullptr;
    if ((long long)out_size >= nd + N) { outQ = (float*)d_out; outI = (float*)d_out + nd; }
    else if ((long long)out_size == nd) { outQ = (float*)d_out; }
    else { outI = (float*)d_out; }

    const int smembytes = 32768 + 8192 + 512 + RPT * CAP * 2;   // 53760 B
    cudaFuncSetAttribute(vq_main, cudaFuncAttributeMaxDynamicSharedMemorySize,
                         smembytes);

    prepA<<<(K + 255) / 256, 256>>>(W, K);
    prepB<<<1, 256>>>(K);
    prepC<<<(K + 255) / 256, 256>>>(W, K);
    vq_main<<<N / RPT, 256, smembytes>>>(X, W, outQ, outI, K);
}